// round 1
// baseline (speedup 1.0000x reference)
#include <cuda_runtime.h>
#include <math.h>

#define NN    256
#define BATCH 16
#define WID   64
#define MD    16
#define HSZ   (BATCH*WID*NN*NN)

// ---------------- scratch (device globals; no allocations) ----------------
__device__ __align__(16) float g_h0[HSZ];                       // 268 MB
__device__ __align__(16) float g_h1[HSZ];                       // 268 MB
__device__ __align__(16) float g_fy [BATCH*WID*NN*MD*2];        // 33.5 MB
__device__ __align__(16) float g_fxy[BATCH*WID*MD*MD*2];        // 2 MB
__device__ __align__(16) float g_ymix[BATCH*WID*MD*MD*2];       // 2 MB
__device__ __align__(16) float g_gx [BATCH*WID*NN*MD*2];        // 33.5 MB
__device__ __align__(16) float2 g_tab[NN];

__device__ __forceinline__ float* hbuf(int s) { return s ? g_h1 : g_h0; }

// ---------------- twiddle table: cos/sin(2*pi*m/256) ----------------
__global__ void init_tab_kernel() {
    int m = threadIdx.x;
    double a = (2.0 * 3.14159265358979323846 * (double)m) / 256.0;
    g_tab[m] = make_float2((float)cos(a), (float)sin(a));
}

// ---------------- lift: h[b,w,x,y] = sum_c x[b,c,x,y]*W[w,c] + bias[w] ----------------
__global__ __launch_bounds__(256) void fc0_kernel(const float* __restrict__ x,
                                                  const float* __restrict__ w,
                                                  const float* __restrict__ bias) {
    __shared__ float ws[WID*3];
    __shared__ float bs[WID];
    int t = threadIdx.x;
    if (t < WID*3) ws[t] = w[t];
    if (t < WID)   bs[t] = bias[t];
    __syncthreads();
    int p  = blockIdx.x * 256 + t;       // global pixel (b, xy)
    int b  = p >> 16;
    int xy = p & 65535;
    float v0 = x[(b*3 + 0)*65536 + xy];
    float v1 = x[(b*3 + 1)*65536 + xy];
    float v2 = x[(b*3 + 2)*65536 + xy];
    float* ho = g_h0 + (size_t)b * WID * 65536 + xy;
#pragma unroll
    for (int o = 0; o < WID; o++)
        ho[(size_t)o*65536] = fmaf(ws[o*3], v0, fmaf(ws[o*3+1], v1, fmaf(ws[o*3+2], v2, bs[o])));
}

// ---------------- stage 1: Fy[row,k2] = sum_y h[row,y] * e^{-2pi i k2 y / 256} ----------------
// rows = b*64*256 + c*256 + x  (262144 rows). Block: 64 rows x 32 cols, 256 threads.
__global__ __launch_bounds__(256) void dfty_fwd(int src) {
    const float* __restrict__ h = hbuf(src);
    __shared__ float T[NN][32];     // [y][2k]=cos, [2k+1]=-sin
    __shared__ float As[64][33];
    int tid = threadIdx.x;
    for (int idx = tid; idx < NN*MD; idx += 256) {
        int y = idx >> 4, k = idx & 15;
        float2 e = g_tab[(y*k) & 255];
        T[y][2*k]   = e.x;
        T[y][2*k+1] = -e.y;
    }
    int row0 = blockIdx.x * 64;
    int ty = tid >> 3, tx = tid & 7;
    float acc0[4] = {0.f,0.f,0.f,0.f};
    float acc1[4] = {0.f,0.f,0.f,0.f};
    for (int kk = 0; kk < 8; kk++) {
        __syncthreads();
#pragma unroll
        for (int j = 0; j < 2; j++) {
            int slot = tid + j*256;
            int r = slot >> 3, c4 = slot & 7;
            float4 v = *reinterpret_cast<const float4*>(h + (size_t)(row0 + r)*NN + kk*32 + c4*4);
            As[r][c4*4+0] = v.x; As[r][c4*4+1] = v.y; As[r][c4*4+2] = v.z; As[r][c4*4+3] = v.w;
        }
        __syncthreads();
#pragma unroll
        for (int y = 0; y < 32; y++) {
            float a0 = As[ty][y];
            float a1 = As[ty+32][y];
            float4 tv = *reinterpret_cast<const float4*>(&T[kk*32 + y][tx*4]);
            acc0[0] = fmaf(a0, tv.x, acc0[0]);
            acc0[1] = fmaf(a0, tv.y, acc0[1]);
            acc0[2] = fmaf(a0, tv.z, acc0[2]);
            acc0[3] = fmaf(a0, tv.w, acc0[3]);
            acc1[0] = fmaf(a1, tv.x, acc1[0]);
            acc1[1] = fmaf(a1, tv.y, acc1[1]);
            acc1[2] = fmaf(a1, tv.z, acc1[2]);
            acc1[3] = fmaf(a1, tv.w, acc1[3]);
        }
    }
    *reinterpret_cast<float4*>(g_fy + (size_t)(row0 + ty   )*32 + tx*4) = make_float4(acc0[0],acc0[1],acc0[2],acc0[3]);
    *reinterpret_cast<float4*>(g_fy + (size_t)(row0 + ty+32)*32 + tx*4) = make_float4(acc1[0],acc1[1],acc1[2],acc1[3]);
}

// ---------------- stage 2a: Fxy[bc,k1,k2] = sum_x Fy[bc,x,k2] * e^{-2pi i k1 x / 256} ----------------
__global__ __launch_bounds__(256) void dftx_fwd() {
    __shared__ float2 Fs[NN*MD];   // [x][k2]
    __shared__ float2 tb[NN];
    int tid = threadIdx.x;
    int bc  = blockIdx.x;
    const float4* src = reinterpret_cast<const float4*>(g_fy + (size_t)bc*NN*32);
    float4* fd = reinterpret_cast<float4*>(Fs);
#pragma unroll
    for (int j = 0; j < 8; j++) fd[tid + j*256] = src[tid + j*256];
    tb[tid] = g_tab[tid];
    __syncthreads();
    int k1 = tid >> 4, k2 = tid & 15;
    float re = 0.f, im = 0.f;
    int m = 0;
    for (int x = 0; x < NN; x++) {
        float2 F = Fs[x*16 + k2];
        float2 e = tb[m];
        m = (m + k1) & 255;
        re = fmaf(F.x, e.x, re); re = fmaf(F.y, e.y, re);      // Re(F * conj(e))
        im = fmaf(F.y, e.x, im); im = fmaf(-F.x, e.y, im);     // Im(F * conj(e))
    }
    g_fxy[(size_t)bc*512 + tid*2    ] = re;
    g_fxy[(size_t)bc*512 + tid*2 + 1] = im;
}

// ---------------- stage 2b: per-mode channel mix, Y = (1/65536) * sum_i X_i * W[i,o] ----------------
__global__ __launch_bounds__(256) void mode_mix(const float* __restrict__ sw) {
    __shared__ float2 Ws[WID*WID];  // [i*64+o]
    __shared__ float2 Xs[WID];
    __shared__ float2 red[256];
    int tid  = threadIdx.x;
    int mode = blockIdx.x;
    for (int idx = tid; idx < WID*WID; idx += 256) {
        const float* p = sw + ((size_t)idx*256 + mode)*2;
        Ws[idx] = make_float2(p[0], p[1]);
    }
    int o = tid & 63, ig = tid >> 6;
    const float sc = 1.0f / 65536.0f;
    for (int b = 0; b < BATCH; b++) {
        __syncthreads();
        if (tid < 64) {
            const float* p = g_fxy + ((size_t)(b*64 + tid)*256 + mode)*2;
            Xs[tid] = make_float2(p[0], p[1]);
        }
        __syncthreads();
        float2 a = make_float2(0.f, 0.f);
#pragma unroll
        for (int ii = 0; ii < 16; ii++) {
            int i = ig*16 + ii;
            float2 X = Xs[i];
            float2 Wv = Ws[i*64 + o];
            a.x = fmaf(X.x, Wv.x, a.x); a.x = fmaf(-X.y, Wv.y, a.x);
            a.y = fmaf(X.x, Wv.y, a.y); a.y = fmaf( X.y, Wv.x, a.y);
        }
        red[tid] = a;
        __syncthreads();
        if (tid < 64) {
            float2 s0 = red[tid], s1 = red[tid+64], s2 = red[tid+128], s3 = red[tid+192];
            float* p = g_ymix + ((size_t)(b*64 + tid)*256 + mode)*2;
            p[0] = (s0.x + s1.x + s2.x + s3.x) * sc;
            p[1] = (s0.y + s1.y + s2.y + s3.y) * sc;
        }
    }
}

// ---------------- stage 2c: g[bo,x,k2] = sum_k1 Y[bo,k1,k2] * e^{+2pi i k1 x / 256} ----------------
__global__ __launch_bounds__(256) void dftx_inv() {
    __shared__ float2 Ys[256];
    __shared__ float2 tb[NN];
    int tid = threadIdx.x;
    int bo  = blockIdx.x;
    Ys[tid] = reinterpret_cast<const float2*>(g_ymix)[(size_t)bo*256 + tid];
    tb[tid] = g_tab[tid];
    __syncthreads();
    int x = tid;
    float2 acc[16];
#pragma unroll
    for (int k2 = 0; k2 < 16; k2++) acc[k2] = make_float2(0.f, 0.f);
    int m = 0;
#pragma unroll
    for (int k1 = 0; k1 < 16; k1++) {
        float2 e = tb[m];
        m = (m + x) & 255;
#pragma unroll
        for (int k2 = 0; k2 < 16; k2++) {
            float2 Yv = Ys[k1*16 + k2];
            acc[k2].x = fmaf(Yv.x, e.x, acc[k2].x); acc[k2].x = fmaf(-Yv.y, e.y, acc[k2].x);
            acc[k2].y = fmaf(Yv.x, e.y, acc[k2].y); acc[k2].y = fmaf( Yv.y, e.x, acc[k2].y);
        }
    }
    float* dst = g_gx + ((size_t)bo*256 + x)*32;
#pragma unroll
    for (int k2 = 0; k2 < 16; k2++) { dst[2*k2] = acc[k2].x; dst[2*k2+1] = acc[k2].y; }
}

// ---------------- stage 3 (fused): out = GELU( invDFT_y(g) + conv1x1(h) + bias ) ----------------
// Block per (b, x-row): stages h[64][256], cw^T[64][68], g-row[64][34] (k2>=1 pre-doubled).
#define CSG_FLOATS (64*256 + 64*68 + 64*34 + 256*2 + 64)
#define CSG_SMEM   (CSG_FLOATS * 4)

__global__ __launch_bounds__(256, 2) void conv_spec_gelu(int src, int dst,
                                                         const float* __restrict__ cw,
                                                         const float* __restrict__ cb,
                                                         int hasSpec) {
    extern __shared__ float smf[];
    float*  hs  = smf;                         // [64][256]
    float*  cws = smf + 64*256;                // [64][68], [i][o]
    float*  gs  = cws + 64*68;                 // [64][34], [o][2*k2 + ri]
    float2* tb  = reinterpret_cast<float2*>(gs + 64*34);
    float*  cbs = reinterpret_cast<float*>(tb + 256);

    const float* __restrict__ hin  = hbuf(src);
    float* __restrict__       hout = hbuf(dst);
    int tid = threadIdx.x;
    int b = blockIdx.x >> 8;
    int x = blockIdx.x & 255;

    const float* hbase = hin + ((size_t)b*64*256 + x)*256;
#pragma unroll
    for (int j = 0; j < 16; j++) {
        int slot = tid + j*256;
        int i = slot >> 6, c4 = slot & 63;
        float4 v = *reinterpret_cast<const float4*>(hbase + (size_t)i*65536 + c4*4);
        *reinterpret_cast<float4*>(&hs[i*256 + c4*4]) = v;
    }
    for (int idx = tid; idx < 4096; idx += 256) {
        int o = idx >> 6, i = idx & 63;
        cws[i*68 + o] = cw[idx];               // coalesced read, transposed store
    }
    if (hasSpec) {
        const float* gbase = g_gx + ((size_t)b*64*256 + x)*32;
#pragma unroll
        for (int j = 0; j < 8; j++) {
            int slot = tid + j*256;
            int o = slot >> 5, c = slot & 31;
            float v = gbase[(size_t)o*8192 + c];
            gs[o*34 + c] = (c >= 2) ? 2.f*v : v;  // double all k2>=1 terms
        }
    }
    tb[tid] = g_tab[tid];
    if (tid < 64) cbs[tid] = cb[tid];
    __syncthreads();

    int o0 = (tid & 7) * 8;
    int y0 = (tid >> 3) * 8;
    float acc[8][8];
#pragma unroll
    for (int a = 0; a < 8; a++)
#pragma unroll
        for (int c = 0; c < 8; c++) acc[a][c] = 0.f;

    if (hasSpec) {
#pragma unroll
        for (int k2 = 0; k2 < 16; k2++) {
            float gr[8], gi[8];
#pragma unroll
            for (int oo = 0; oo < 8; oo++) {
                gr[oo] = gs[(o0+oo)*34 + 2*k2];
                gi[oo] = gs[(o0+oo)*34 + 2*k2 + 1];
            }
            int m = (k2 * y0) & 255;
#pragma unroll
            for (int yy = 0; yy < 8; yy++) {
                float2 cc = tb[m];
                m = (m + k2) & 255;
#pragma unroll
                for (int oo = 0; oo < 8; oo++) {
                    acc[oo][yy] = fmaf(gr[oo], cc.x, acc[oo][yy]);
                    acc[oo][yy] = fmaf(-gi[oo], cc.y, acc[oo][yy]);
                }
            }
        }
    }

#pragma unroll 4
    for (int i = 0; i < 64; i++) {
        float4 hA = *reinterpret_cast<const float4*>(&hs[i*256 + y0]);
        float4 hB = *reinterpret_cast<const float4*>(&hs[i*256 + y0 + 4]);
        float4 wA = *reinterpret_cast<const float4*>(&cws[i*68 + o0]);
        float4 wB = *reinterpret_cast<const float4*>(&cws[i*68 + o0 + 4]);
        float hv[8] = {hA.x,hA.y,hA.z,hA.w,hB.x,hB.y,hB.z,hB.w};
        float wv[8] = {wA.x,wA.y,wA.z,wA.w,wB.x,wB.y,wB.z,wB.w};
#pragma unroll
        for (int oo = 0; oo < 8; oo++)
#pragma unroll
            for (int yy = 0; yy < 8; yy++)
                acc[oo][yy] = fmaf(wv[oo], hv[yy], acc[oo][yy]);
    }

    float* obase = hout + ((size_t)b*64*256 + x)*256;
#pragma unroll
    for (int oo = 0; oo < 8; oo++) {
        int o = o0 + oo;
        float bias = cbs[o];
        float res[8];
#pragma unroll
        for (int yy = 0; yy < 8; yy++) {
            float v = acc[oo][yy] + bias;
            res[yy] = 0.5f * v * (1.0f + erff(v * 0.70710678118654752f));  // exact GELU
        }
        float4* dp = reinterpret_cast<float4*>(obase + (size_t)o*65536 + y0);
        dp[0] = make_float4(res[0], res[1], res[2], res[3]);
        dp[1] = make_float4(res[4], res[5], res[6], res[7]);
    }
}

// ---------------- head: out[b,0,x,y] = sum_f h[b,f,x,y]*w[f] + bias ----------------
__global__ __launch_bounds__(256) void fc2_kernel(int src, const float* __restrict__ w,
                                                  const float* __restrict__ bias,
                                                  float* __restrict__ out) {
    __shared__ float ws[64];
    int tid = threadIdx.x;
    if (tid < 64) ws[tid] = w[tid];
    __syncthreads();
    int p  = blockIdx.x * 256 + tid;
    int b  = p >> 16;
    int xy = p & 65535;
    const float* hp = hbuf(src) + (size_t)b*64*65536 + xy;
    float acc = bias[0];
#pragma unroll
    for (int f = 0; f < 64; f++) acc = fmaf(hp[(size_t)f*65536], ws[f], acc);
    out[p] = acc;
}

// ---------------- launch ----------------
extern "C" void kernel_launch(void* const* d_in, const int* in_sizes, int n_in,
                              void* d_out, int out_size) {
    const float* x     = (const float*)d_in[0];
    const float* fc0_w = (const float*)d_in[1];
    const float* fc0_b = (const float*)d_in[2];
    const float* sw[4] = {(const float*)d_in[3], (const float*)d_in[4],
                          (const float*)d_in[5], (const float*)d_in[6]};
    const float* cw[4] = {(const float*)d_in[7], (const float*)d_in[9],
                          (const float*)d_in[11], (const float*)d_in[13]};
    const float* cb[4] = {(const float*)d_in[8], (const float*)d_in[10],
                          (const float*)d_in[12], (const float*)d_in[14]};
    const float* fc1_w = (const float*)d_in[15];
    const float* fc1_b = (const float*)d_in[16];
    const float* fc2_w = (const float*)d_in[17];
    const float* fc2_b = (const float*)d_in[18];
    float* out = (float*)d_out;

    cudaFuncSetAttribute(conv_spec_gelu, cudaFuncAttributeMaxDynamicSharedMemorySize, CSG_SMEM);

    init_tab_kernel<<<1, 256>>>();
    fc0_kernel<<<4096, 256>>>(x, fc0_w, fc0_b);

    int src = 0;
    for (int l = 0; l < 4; l++) {
        dfty_fwd<<<4096, 256>>>(src);
        dftx_fwd<<<1024, 256>>>();
        mode_mix<<<256, 256>>>(sw[l]);
        dftx_inv<<<1024, 256>>>();
        conv_spec_gelu<<<4096, 256, CSG_SMEM>>>(src, 1 - src, cw[l], cb[l], 1);
        src = 1 - src;
    }
    // fc1 + GELU: same fused kernel, no spectral term (fc1_w layout [f][w] == cw layout [o][i])
    conv_spec_gelu<<<4096, 256, CSG_SMEM>>>(src, 1 - src, fc1_w, fc1_b, 0);
    src = 1 - src;
    fc2_kernel<<<4096, 256>>>(src, fc2_w, fc2_b, out);
}

// round 2
// speedup vs baseline: 1.1163x; 1.1163x over previous
#include <cuda_runtime.h>
#include <math.h>

#define NN    256
#define BATCH 16
#define WID   64
#define MD    16
#define HSZ   (BATCH*WID*NN*NN)

typedef unsigned long long u64;

// ---------------- f32x2 packed helpers ----------------
__device__ __forceinline__ u64 pack2(float lo, float hi) {
    u64 r; asm("mov.b64 %0,{%1,%2};" : "=l"(r) : "f"(lo), "f"(hi)); return r;
}
__device__ __forceinline__ void unpack2(u64 v, float &lo, float &hi) {
    asm("mov.b64 {%0,%1},%2;" : "=f"(lo), "=f"(hi) : "l"(v));
}
__device__ __forceinline__ void ffma2(u64 &d, u64 a, u64 b) {
    asm("fma.rn.f32x2 %0,%1,%2,%0;" : "+l"(d) : "l"(a), "l"(b));
}

// ---------------- scratch (device globals; no allocations) ----------------
__device__ __align__(16) float g_h0[HSZ];
__device__ __align__(16) float g_h1[HSZ];
__device__ __align__(16) float g_fy [BATCH*WID*NN*MD*2];
__device__ __align__(16) float g_fxy[BATCH*WID*MD*MD*2];
__device__ __align__(16) float g_ymix[BATCH*WID*MD*MD*2];
__device__ __align__(16) float g_gx [BATCH*WID*NN*MD*2];
__device__ __align__(16) float2 g_tab[NN];

__device__ __forceinline__ float* hbuf(int s) { return s ? g_h1 : g_h0; }

__global__ void init_tab_kernel() {
    int m = threadIdx.x;
    double a = (2.0 * 3.14159265358979323846 * (double)m) / 256.0;
    g_tab[m] = make_float2((float)cos(a), (float)sin(a));
}

// ---------------- shared Fy stage ----------------
// res: [64][SR] in smem (full gelu/lift output row for (b,x)); tbl: u64[128][17],
// tbl[y][k] = (cos(2pi k y/256), -sin(...)). Uses y<->y+128 parity fold.
#define SR 260

__device__ __forceinline__ void fy_stage(const float* __restrict__ res,
                                         const u64* __restrict__ tbl,
                                         int b, int xx, int tid) {
    int o = tid >> 2, q = tid & 3;
    const float* rp = res + o * SR;
    const u64* tq = tbl + q * 4;
    u64 a0 = 0, a1 = 0, a2 = 0, a3 = 0;
#pragma unroll 4
    for (int y = 0; y < 128; y++) {
        float lo = rp[y], hi = rp[y + 128];
        float sp = lo + hi, sm = lo - hi;
        u64 psp = pack2(sp, sp);
        u64 psm = pack2(sm, sm);
        const u64* tr = tq + y * 17;
        ffma2(a0, psp, tr[0]);   // k = 4q+0 (even)
        ffma2(a1, psm, tr[1]);   // k = 4q+1 (odd)
        ffma2(a2, psp, tr[2]);
        ffma2(a3, psm, tr[3]);
    }
    float* fp = g_fy + (((size_t)(b * 64 + o) * 256 + xx) << 5) + q * 8;
    reinterpret_cast<ulonglong2*>(fp)[0] = make_ulonglong2(a0, a1);
    reinterpret_cast<ulonglong2*>(fp)[1] = make_ulonglong2(a2, a3);
}

__device__ __forceinline__ void build_tbl(u64* tbl, int tid) {
    for (int idx = tid; idx < 2048; idx += 256) {
        int y = idx >> 4, k = idx & 15;
        float2 e = g_tab[(y * k) & 255];
        tbl[y * 17 + k] = pack2(e.x, -e.y);
    }
}

// ---------------- lift + Fy ----------------
#define F0_TBL 16640
#define F0_XS  (F0_TBL + 4352)
#define F0_WS  (F0_XS + 768)
#define F0_BS  (F0_WS + 192)
#define F0_FLOATS (F0_BS + 64)
#define F0_SMEM (F0_FLOATS * 4)

__global__ __launch_bounds__(256, 2) void fc0_fy(const float* __restrict__ x,
                                                 const float* __restrict__ w,
                                                 const float* __restrict__ bias) {
    extern __shared__ float smf[];
    int tid = threadIdx.x;
    int b = blockIdx.x >> 8, xx = blockIdx.x & 255;
    float* xs = smf + F0_XS;
    float* ws = smf + F0_WS;
    float* bs = smf + F0_BS;
    u64* tbl = reinterpret_cast<u64*>(smf + F0_TBL);

    for (int idx = tid; idx < 768; idx += 256) {
        int c = idx >> 8, y = idx & 255;
        xs[idx] = x[((size_t)(b * 3 + c) * 256 + xx) * 256 + y];
    }
    if (tid < 192) ws[tid] = w[tid];
    if (tid < 64)  bs[tid] = bias[tid];
    build_tbl(tbl, tid);
    __syncthreads();

    int o = tid >> 2, yc = (tid & 3) * 64;
    float w0 = ws[o * 3], w1 = ws[o * 3 + 1], w2v = ws[o * 3 + 2], bb = bs[o];
#pragma unroll 8
    for (int j = 0; j < 64; j++) {
        int y = yc + j;
        smf[o * SR + y] = fmaf(w0, xs[y], fmaf(w1, xs[256 + y], fmaf(w2v, xs[512 + y], bb)));
    }
    __syncthreads();

    // write h0 row, coalesced float4s
#pragma unroll
    for (int j = 0; j < 16; j++) {
        int slot = tid + j * 256;
        int oo = slot >> 6, y4 = (slot & 63) * 4;
        float4 v = *reinterpret_cast<const float4*>(&smf[oo * SR + y4]);
        *reinterpret_cast<float4*>(g_h0 + ((size_t)(b * 64 + oo) << 16) + xx * 256 + y4) = v;
    }
    fy_stage(smf, tbl, b, xx, tid);
}

// ---------------- stage 2a: x-forward DFT (unchanged from R1) ----------------
__global__ __launch_bounds__(256) void dftx_fwd() {
    __shared__ float2 Fs[NN * MD];
    __shared__ float2 tb[NN];
    int tid = threadIdx.x;
    int bc  = blockIdx.x;
    const float4* src = reinterpret_cast<const float4*>(g_fy + (size_t)bc * NN * 32);
    float4* fd = reinterpret_cast<float4*>(Fs);
#pragma unroll
    for (int j = 0; j < 8; j++) fd[tid + j * 256] = src[tid + j * 256];
    tb[tid] = g_tab[tid];
    __syncthreads();
    int k1 = tid >> 4, k2 = tid & 15;
    float re = 0.f, im = 0.f;
    int m = 0;
    for (int x = 0; x < NN; x++) {
        float2 F = Fs[x * 16 + k2];
        float2 e = tb[m];
        m = (m + k1) & 255;
        re = fmaf(F.x, e.x, re); re = fmaf(F.y, e.y, re);
        im = fmaf(F.y, e.x, im); im = fmaf(-F.x, e.y, im);
    }
    g_fxy[(size_t)bc * 512 + tid * 2    ] = re;
    g_fxy[(size_t)bc * 512 + tid * 2 + 1] = im;
}

// ---------------- stage 2b: per-mode channel mix (unchanged) ----------------
__global__ __launch_bounds__(256) void mode_mix(const float* __restrict__ sw) {
    __shared__ float2 Ws[WID * WID];
    __shared__ float2 Xs[WID];
    __shared__ float2 red[256];
    int tid  = threadIdx.x;
    int mode = blockIdx.x;
    for (int idx = tid; idx < WID * WID; idx += 256) {
        const float* p = sw + ((size_t)idx * 256 + mode) * 2;
        Ws[idx] = make_float2(p[0], p[1]);
    }
    int o = tid & 63, ig = tid >> 6;
    const float sc = 1.0f / 65536.0f;
    for (int b = 0; b < BATCH; b++) {
        __syncthreads();
        if (tid < 64) {
            const float* p = g_fxy + ((size_t)(b * 64 + tid) * 256 + mode) * 2;
            Xs[tid] = make_float2(p[0], p[1]);
        }
        __syncthreads();
        float2 a = make_float2(0.f, 0.f);
#pragma unroll
        for (int ii = 0; ii < 16; ii++) {
            int i = ig * 16 + ii;
            float2 X = Xs[i];
            float2 Wv = Ws[i * 64 + o];
            a.x = fmaf(X.x, Wv.x, a.x); a.x = fmaf(-X.y, Wv.y, a.x);
            a.y = fmaf(X.x, Wv.y, a.y); a.y = fmaf( X.y, Wv.x, a.y);
        }
        red[tid] = a;
        __syncthreads();
        if (tid < 64) {
            float2 s0 = red[tid], s1 = red[tid + 64], s2 = red[tid + 128], s3 = red[tid + 192];
            float* p = g_ymix + ((size_t)(b * 64 + tid) * 256 + mode) * 2;
            p[0] = (s0.x + s1.x + s2.x + s3.x) * sc;
            p[1] = (s0.y + s1.y + s2.y + s3.y) * sc;
        }
    }
}

// ---------------- stage 2c: x-inverse DFT (unchanged) ----------------
__global__ __launch_bounds__(256) void dftx_inv() {
    __shared__ float2 Ys[256];
    __shared__ float2 tb[NN];
    int tid = threadIdx.x;
    int bo  = blockIdx.x;
    Ys[tid] = reinterpret_cast<const float2*>(g_ymix)[(size_t)bo * 256 + tid];
    tb[tid] = g_tab[tid];
    __syncthreads();
    int x = tid;
    float2 acc[16];
#pragma unroll
    for (int k2 = 0; k2 < 16; k2++) acc[k2] = make_float2(0.f, 0.f);
    int m = 0;
#pragma unroll
    for (int k1 = 0; k1 < 16; k1++) {
        float2 e = tb[m];
        m = (m + x) & 255;
#pragma unroll
        for (int k2 = 0; k2 < 16; k2++) {
            float2 Yv = Ys[k1 * 16 + k2];
            acc[k2].x = fmaf(Yv.x, e.x, acc[k2].x); acc[k2].x = fmaf(-Yv.y, e.y, acc[k2].x);
            acc[k2].y = fmaf(Yv.x, e.y, acc[k2].y); acc[k2].y = fmaf( Yv.y, e.x, acc[k2].y);
        }
    }
    float* dst = g_gx + ((size_t)bo * 256 + x) * 32;
#pragma unroll
    for (int k2 = 0; k2 < 16; k2++) { dst[2 * k2] = acc[k2].x; dst[2 * k2 + 1] = acc[k2].y; }
}

// ---------------- stage 3 (mega-fused): conv1x1 + spectral-inverse-y + GELU
//                  (+ optional Fy of the output, + optional fc2 head) ----------------
#define OFF_CW  16384
#define OFF_TBL 20736
#define OFF_GR  25088
#define OFF_GI  26176
#define OFF_CB  27264
#define OFF_HW  27328
#define OFF_HB  27392
#define CONV_FLOATS 27400
#define CONV_SMEM   (CONV_FLOATS * 4)

__global__ __launch_bounds__(256, 2) void conv_fused(int src, int dst,
                                                     const float* __restrict__ cw,
                                                     const float* __restrict__ cb,
                                                     int hasSpec, int doFy, int doHead,
                                                     const float* __restrict__ hw,
                                                     const float* __restrict__ hb,
                                                     float* __restrict__ out) {
    extern __shared__ float smf[];
    float* cws = smf + OFF_CW;
    u64*  tbl  = reinterpret_cast<u64*>(smf + OFF_TBL);
    float* gsRe = smf + OFF_GR;
    float* gsIm = smf + OFF_GI;
    float* cbs  = smf + OFF_CB;

    const float* __restrict__ hin = hbuf(src);
    float* __restrict__ hout = hbuf(dst);
    int tid = threadIdx.x;
    int b = blockIdx.x >> 8;
    int xx = blockIdx.x & 255;

    // ---- staging ----
    const float* hbase = hin + ((size_t)b * 64 * 256 + xx) * 256;
#pragma unroll
    for (int j = 0; j < 16; j++) {
        int slot = tid + j * 256;
        int i = slot >> 6, c4 = slot & 63;
        float4 v = *reinterpret_cast<const float4*>(hbase + (size_t)i * 65536 + c4 * 4);
        *reinterpret_cast<float4*>(&smf[i * 256 + c4 * 4]) = v;
    }
    for (int idx = tid; idx < 4096; idx += 256) {
        int o = idx >> 6, i = idx & 63;
        cws[i * 68 + o] = cw[idx];           // transpose: cw[o][i] -> cws[i][o]
    }
    build_tbl(tbl, tid);
    if (hasSpec) {
        for (int idx = tid; idx < 1024; idx += 256) {
            int k2 = idx >> 6, o = idx & 63;
            const float* p = g_gx + (((size_t)(b * 64 + o) * 256 + xx) << 5) + 2 * k2;
            float d = (k2 > 0) ? 2.f : 1.f;
            gsRe[k2 * 68 + o] = d * p[0];
            gsIm[k2 * 68 + o] = d * p[1];
        }
    }
    if (tid < 64) cbs[tid] = cb[tid];
    if (doHead) {
        if (tid < 64) smf[OFF_HW + tid] = hw[tid];
        if (tid == 0) smf[OFF_HB] = hb[0];
    }
    __syncthreads();

    int o0 = (tid & 7) * 8;
    int y0 = (tid >> 3) * 8;
    u64 acc[4][8];
#pragma unroll
    for (int a = 0; a < 4; a++)
#pragma unroll
        for (int c = 0; c < 8; c++) acc[a][c] = 0ull;

    // ---- spectral inverse-y into acc ----
    if (hasSpec) {
        int ylo = y0 & 127;
        bool up = (y0 >= 128);
#pragma unroll 1
        for (int k2 = 0; k2 < 16; k2++) {
            float sg = (up && (k2 & 1)) ? -1.f : 1.f;
            const float* grp = gsRe + k2 * 68 + o0;
            const float* gip = gsIm + k2 * 68 + o0;
            float4 ra = *reinterpret_cast<const float4*>(grp);
            float4 rb = *reinterpret_cast<const float4*>(grp + 4);
            float4 ia = *reinterpret_cast<const float4*>(gip);
            float4 ib = *reinterpret_cast<const float4*>(gip + 4);
            u64 gr2[4] = {pack2(ra.x, ra.y), pack2(ra.z, ra.w), pack2(rb.x, rb.y), pack2(rb.z, rb.w)};
            u64 gi2[4] = {pack2(ia.x, ia.y), pack2(ia.z, ia.w), pack2(ib.x, ib.y), pack2(ib.z, ib.w)};
            const u64* tp = tbl + ylo * 17 + k2;
#pragma unroll
            for (int yy = 0; yy < 8; yy++) {
                float c, s; unpack2(tp[yy * 17], c, s);   // c=cos, s=-sin (pre-negated)
                u64 pc = pack2(sg * c, sg * c);
                u64 ps = pack2(sg * s, sg * s);
                ffma2(acc[0][yy], gr2[0], pc); ffma2(acc[0][yy], gi2[0], ps);
                ffma2(acc[1][yy], gr2[1], pc); ffma2(acc[1][yy], gi2[1], ps);
                ffma2(acc[2][yy], gr2[2], pc); ffma2(acc[2][yy], gi2[2], ps);
                ffma2(acc[3][yy], gr2[3], pc); ffma2(acc[3][yy], gi2[3], ps);
            }
        }
    }

    // ---- conv1x1 mainloop (packed o-pairs) ----
#pragma unroll 4
    for (int i = 0; i < 64; i++) {
        ulonglong2 wA = *reinterpret_cast<const ulonglong2*>(cws + i * 68 + o0);
        ulonglong2 wB = *reinterpret_cast<const ulonglong2*>(cws + i * 68 + o0 + 4);
        float4 hA = *reinterpret_cast<const float4*>(smf + i * 256 + y0);
        float4 hB = *reinterpret_cast<const float4*>(smf + i * 256 + y0 + 4);
        u64 w2[4] = {wA.x, wA.y, wB.x, wB.y};
        float hv[8] = {hA.x, hA.y, hA.z, hA.w, hB.x, hB.y, hB.z, hB.w};
#pragma unroll
        for (int yy = 0; yy < 8; yy++) {
            u64 h2 = pack2(hv[yy], hv[yy]);
            ffma2(acc[0][yy], w2[0], h2);
            ffma2(acc[1][yy], w2[1], h2);
            ffma2(acc[2][yy], w2[2], h2);
            ffma2(acc[3][yy], w2[3], h2);
        }
    }

    // ---- bias + exact GELU, write hout and/or res smem ----
    __syncthreads();   // all hs/cws reads done; res may overwrite
    int writeRes = doFy | doHead;
#pragma unroll
    for (int oop = 0; oop < 4; oop++) {
        int oE = o0 + oop * 2, oO = oE + 1;
        float bE = cbs[oE], bO = cbs[oO];
        float vE[8], vO[8];
#pragma unroll
        for (int yy = 0; yy < 8; yy++) {
            float a, bb; unpack2(acc[oop][yy], a, bb);
            float v = a + bE;
            vE[yy] = 0.5f * v * (1.0f + erff(v * 0.70710678118654752f));
            float w = bb + bO;
            vO[yy] = 0.5f * w * (1.0f + erff(w * 0.70710678118654752f));
        }
        if (writeRes) {
            *reinterpret_cast<float4*>(&smf[oE * SR + y0    ]) = make_float4(vE[0], vE[1], vE[2], vE[3]);
            *reinterpret_cast<float4*>(&smf[oE * SR + y0 + 4]) = make_float4(vE[4], vE[5], vE[6], vE[7]);
            *reinterpret_cast<float4*>(&smf[oO * SR + y0    ]) = make_float4(vO[0], vO[1], vO[2], vO[3]);
            *reinterpret_cast<float4*>(&smf[oO * SR + y0 + 4]) = make_float4(vO[4], vO[5], vO[6], vO[7]);
        }
        if (!doHead) {
            float4* dE = reinterpret_cast<float4*>(hout + ((size_t)(b * 64 + oE) << 16) + xx * 256 + y0);
            dE[0] = make_float4(vE[0], vE[1], vE[2], vE[3]);
            dE[1] = make_float4(vE[4], vE[5], vE[6], vE[7]);
            float4* dO = reinterpret_cast<float4*>(hout + ((size_t)(b * 64 + oO) << 16) + xx * 256 + y0);
            dO[0] = make_float4(vO[0], vO[1], vO[2], vO[3]);
            dO[1] = make_float4(vO[4], vO[5], vO[6], vO[7]);
        }
    }

    if (doFy) {
        __syncthreads();
        fy_stage(smf, tbl, b, xx, tid);
    }
    if (doHead) {
        __syncthreads();
        const float* hwS = smf + OFF_HW;
        float a = smf[OFF_HB];
        int y = tid;
#pragma unroll 16
        for (int f = 0; f < 64; f++) a = fmaf(smf[f * SR + y], hwS[f], a);
        out[(size_t)b * 65536 + xx * 256 + y] = a;
    }
}

// ---------------- launch ----------------
extern "C" void kernel_launch(void* const* d_in, const int* in_sizes, int n_in,
                              void* d_out, int out_size) {
    const float* x     = (const float*)d_in[0];
    const float* fc0_w = (const float*)d_in[1];
    const float* fc0_b = (const float*)d_in[2];
    const float* sw[4] = {(const float*)d_in[3], (const float*)d_in[4],
                          (const float*)d_in[5], (const float*)d_in[6]};
    const float* cw[4] = {(const float*)d_in[7], (const float*)d_in[9],
                          (const float*)d_in[11], (const float*)d_in[13]};
    const float* cb[4] = {(const float*)d_in[8], (const float*)d_in[10],
                          (const float*)d_in[12], (const float*)d_in[14]};
    const float* fc1_w = (const float*)d_in[15];
    const float* fc1_b = (const float*)d_in[16];
    const float* fc2_w = (const float*)d_in[17];
    const float* fc2_b = (const float*)d_in[18];
    float* out = (float*)d_out;

    cudaFuncSetAttribute(conv_fused, cudaFuncAttributeMaxDynamicSharedMemorySize, CONV_SMEM);
    cudaFuncSetAttribute(fc0_fy,     cudaFuncAttributeMaxDynamicSharedMemorySize, F0_SMEM);

    init_tab_kernel<<<1, 256>>>();
    fc0_fy<<<4096, 256, F0_SMEM>>>(x, fc0_w, fc0_b);   // h0 + Fy(h0)

    int src = 0;
    for (int l = 0; l < 4; l++) {
        dftx_fwd<<<1024, 256>>>();
        mode_mix<<<256, 256>>>(sw[l]);
        dftx_inv<<<1024, 256>>>();
        int doFy = (l < 3) ? 1 : 0;   // layer 4 output feeds only fc1
        conv_fused<<<4096, 256, CONV_SMEM>>>(src, 1 - src, cw[l], cb[l],
                                             1, doFy, 0, nullptr, nullptr, nullptr);
        src = 1 - src;
    }
    // fc1 + GELU + fc2 head fused; writes d_out directly
    conv_fused<<<4096, 256, CONV_SMEM>>>(src, src, fc1_w, fc1_b,
                                         0, 0, 1, fc2_w, fc2_b, out);
}